// round 1
// baseline (speedup 1.0000x reference)
#include <cuda_runtime.h>
#include <math.h>

// ---------------- problem constants ----------------
#define HEADS 2
#define DHEAD 32
#define HW    40
#define HP    42           // padded 42x42
#define NPIX  (HP*HP)      // 1764
#define NH    20
#define NWIN  400
#define NTOK  16
#define LTOT  6400         // NWIN*NTOK
#define NSPLIT 4
#define KSEG  1600         // LTOT/NSPLIT
#define KCHUNK 160
#define SCALE 0.17677669529663687f  // 1/sqrt(32)

// ---------------- scratch (__device__ globals; no allocs allowed) ----------------
__device__ float g_qx[NPIX*64];
__device__ float g_kx[NPIX*64];
__device__ float g_vx[NPIX*64];
__device__ float g_qz[NPIX*64];
__device__ float g_kz[NPIX*64];
__device__ float g_qg[HEADS*LTOT*DHEAD];   // local-attn output == global Q=K=V
__device__ float g_og[HEADS*LTOT*DHEAD];   // global-attn output
__device__ float g_po[HEADS*NSPLIT*LTOT*DHEAD]; // partial (unnormalized) O
__device__ float g_pm[HEADS*NSPLIT*LTOT];       // partial row max
__device__ float g_pl[HEADS*NSPLIT*LTOT];       // partial row expsum

// ---------------- packed f32x2 helpers (Blackwell FFMA2: 2x fp32 throughput) ----------------
static __device__ __forceinline__ float2 ffma2(float2 a, float2 b, float2 c) {
    float2 r;
    asm("fma.rn.f32x2 %0, %1, %2, %3;"
        : "=l"(reinterpret_cast<unsigned long long&>(r))
        : "l"(reinterpret_cast<unsigned long long&>(a)),
          "l"(reinterpret_cast<unsigned long long&>(b)),
          "l"(reinterpret_cast<unsigned long long&>(c)));
    return r;
}
static __device__ __forceinline__ float2 fmul2(float2 a, float2 b) {
    float2 r;
    asm("mul.rn.f32x2 %0, %1, %2;"
        : "=l"(reinterpret_cast<unsigned long long&>(r))
        : "l"(reinterpret_cast<unsigned long long&>(a)),
          "l"(reinterpret_cast<unsigned long long&>(b)));
    return r;
}

static __device__ __forceinline__ int reflect40(int v) {
    // jnp.pad 'reflect' with pad 1: -1 -> 1, 40 -> 38
    return v < 0 ? -v : (v > 39 ? 78 - v : v);
}

// ---------------- kernel 1: conv1x1 projections with reflect pad ----------------
// grid = 42 (one padded row), block = 320 (one thread per output channel of 192+128)
__global__ void proj_kernel(const float* __restrict__ x, const float* __restrict__ z,
                            const float* __restrict__ Wx, const float* __restrict__ bx,
                            const float* __restrict__ Wz, const float* __restrict__ bz) {
    __shared__ __align__(16) float xs[HP*68];
    __shared__ __align__(16) float zs[HP*68];
    int yp = blockIdx.x;
    int ys = reflect40(yp - 1);
    for (int idx = threadIdx.x; idx < HP*64; idx += blockDim.x) {
        int c = idx / HP, xp = idx % HP;
        int xsrc = reflect40(xp - 1);
        int src = c*1600 + ys*HW + xsrc;
        xs[xp*68 + c] = x[src];
        zs[xp*68 + c] = z[src];
    }
    __syncthreads();

    int oc = threadIdx.x;            // 0..319
    const float* wrow; float bias; float* dst; int cout; const float* sm;
    if (oc < 192) {
        wrow = Wx + oc*64; bias = bx[oc];
        int t = oc >> 6; cout = oc & 63;
        dst = (t == 0) ? g_qx : (t == 1 ? g_kx : g_vx);
        sm = xs;
    } else {
        int ozc = oc - 192;
        wrow = Wz + ozc*64; bias = bz[ozc];
        cout = ozc & 63;
        dst = (ozc < 64) ? g_qz : g_kz;
        sm = zs;
    }
    float4 wr[16];
    #pragma unroll
    for (int i = 0; i < 16; i++) wr[i] = ((const float4*)wrow)[i];

    for (int xp = 0; xp < HP; xp++) {
        float acc = bias;
        #pragma unroll
        for (int i = 0; i < 16; i++) {
            float4 v = *(const float4*)(sm + xp*68 + i*4);
            acc += wr[i].x*v.x + wr[i].y*v.y + wr[i].z*v.z + wr[i].w*v.w;
        }
        dst[(yp*HP + xp)*64 + cout] = acc;
    }
}

// ---------------- kernel 2: local 16x16 window attention ----------------
// grid = (400, 2) = (window, head), block = 256 = (i,j)
__global__ void local_attn_kernel(const float* __restrict__ pbeta_p) {
    __shared__ float sq[16*33], sk[16*33], sv[16*33], sqz[16*33], skz[16*33];
    __shared__ float sA[16*17];
    int win = blockIdx.x, h = blockIdx.y;
    int sy = (win / NH) * 2, sx = (win % NH) * 2;
    int tid = threadIdx.x;

    float* tiles[5] = {sq, sk, sv, sqz, skz};
    const float* gsrc[5] = {g_qx, g_kx, g_vx, g_qz, g_kz};
    for (int idx = tid; idx < 640; idx += 256) {
        int t = idx >> 7, rem = idx & 127, tok = rem >> 3, f4 = rem & 7;
        int ty = tok >> 2, tx = tok & 3;
        int pix = (sy + ty)*HP + (sx + tx);
        float4 v = *(const float4*)(gsrc[t] + pix*64 + h*DHEAD + f4*4);
        float* s = tiles[t];
        int so = tok*33 + f4*4;
        s[so] = v.x; s[so+1] = v.y; s[so+2] = v.z; s[so+3] = v.w;
    }
    __syncthreads();

    float pb = *pbeta_p;
    float beta = fmaxf(pb, 0.f) + log1pf(__expf(-fabsf(pb))) + 1e-6f;

    int i = tid >> 4, j = tid & 15;
    float dx = 0.f, dz = 0.f;
    #pragma unroll
    for (int dd = 0; dd < 32; dd++) {
        dx += sq[i*33+dd]  * sk[j*33+dd];
        dz += sqz[i*33+dd] * skz[j*33+dd];
    }
    float s = SCALE * (dx + beta*dz);
    float mx = s;
    #pragma unroll
    for (int off = 8; off; off >>= 1) mx = fmaxf(mx, __shfl_xor_sync(0xffffffffu, mx, off, 16));
    float p = __expf(s - mx);
    float sum = p;
    #pragma unroll
    for (int off = 8; off; off >>= 1) sum += __shfl_xor_sync(0xffffffffu, sum, off, 16);
    sA[i*17 + j] = p / sum;
    __syncthreads();

    #pragma unroll
    for (int pair = 0; pair < 2; pair++) {
        int idx = tid + pair*256;
        int ii = idx >> 5, dd = idx & 31;
        float acc = 0.f;
        #pragma unroll
        for (int jj = 0; jj < 16; jj++) acc += sA[ii*17+jj] * sv[jj*33+dd];
        g_qg[h*(LTOT*DHEAD) + (win*16 + ii)*DHEAD + dd] = acc;
    }
}

// ---------------- kernel 3: global flash attention (Q=K=V=qg), key-split x4 ----------------
// grid = (100, 4, 2) = (qtile of 64 rows, key split, head), block = 64 (one thread per row)
__global__ void __launch_bounds__(64) flash_kernel() {
    __shared__ __align__(16) float ks[KCHUNK*DHEAD];
    int tid = threadIdx.x;
    int row = blockIdx.x*64 + tid;
    int sp  = blockIdx.y;
    int h   = blockIdx.z;
    const float* qbase = g_qg + h*(LTOT*DHEAD);

    float2 q2[16];
    {
        const float4* qp = (const float4*)(qbase + row*DHEAD);
        #pragma unroll
        for (int i = 0; i < 8; i++) {
            float4 v = qp[i];
            q2[2*i]   = make_float2(v.x, v.y);
            q2[2*i+1] = make_float2(v.z, v.w);
        }
    }
    float m = -INFINITY, l = 0.f;
    float2 o2[16];
    #pragma unroll
    for (int i = 0; i < 16; i++) o2[i] = make_float2(0.f, 0.f);

    const float4* gq4 = (const float4*)qbase;
    int k0 = sp * KSEG;
    for (int c = 0; c < KSEG/KCHUNK; c++) {
        int kstart = k0 + c*KCHUNK;
        float4* s4 = (float4*)ks;
        for (int idx = tid; idx < KCHUNK*8; idx += 64) s4[idx] = gq4[kstart*8 + idx];
        __syncthreads();

        #pragma unroll 2
        for (int j = 0; j < KCHUNK; j++) {
            const float4* kr4 = (const float4*)(ks + j*DHEAD);
            float2 kk[16];
            #pragma unroll
            for (int t = 0; t < 8; t++) {
                float4 v = kr4[t];
                kk[2*t]   = make_float2(v.x, v.y);
                kk[2*t+1] = make_float2(v.z, v.w);
            }
            float2 a0 = fmul2(q2[0], kk[0]);
            float2 a1 = fmul2(q2[1], kk[1]);
            float2 a2 = fmul2(q2[2], kk[2]);
            float2 a3 = fmul2(q2[3], kk[3]);
            #pragma unroll
            for (int t = 4; t < 16; t += 4) {
                a0 = ffma2(q2[t],   kk[t],   a0);
                a1 = ffma2(q2[t+1], kk[t+1], a1);
                a2 = ffma2(q2[t+2], kk[t+2], a2);
                a3 = ffma2(q2[t+3], kk[t+3], a3);
            }
            float s = ((a0.x+a0.y) + (a1.x+a1.y)) + ((a2.x+a2.y) + (a3.x+a3.y));
            s *= SCALE;
            if (s <= m) {
                float p = __expf(s - m);
                l += p;
                float2 p2 = make_float2(p, p);
                #pragma unroll
                for (int t = 0; t < 16; t++) o2[t] = ffma2(p2, kk[t], o2[t]);
            } else {
                float r = __expf(m - s);
                m = s;
                l = l*r + 1.f;
                float2 r2 = make_float2(r, r);
                #pragma unroll
                for (int t = 0; t < 16; t++) o2[t] = ffma2(o2[t], r2, kk[t]);
            }
        }
        __syncthreads();
    }

    int pidx = (h*NSPLIT + sp)*LTOT + row;
    g_pm[pidx] = m;
    g_pl[pidx] = l;
    float4* po4 = (float4*)(g_po + (size_t)pidx*DHEAD);
    #pragma unroll
    for (int i = 0; i < 8; i++)
        po4[i] = make_float4(o2[2*i].x, o2[2*i].y, o2[2*i+1].x, o2[2*i+1].y);
}

// ---------------- kernel 4: merge key splits ----------------
// grid = 400, block = 256 : one thread per (row, float4-of-d)
__global__ void merge_kernel() {
    int t = blockIdx.x*256 + threadIdx.x;        // < 12800*8
    int rowf = t >> 3, f4 = t & 7;
    int h = rowf / LTOT, r = rowf % LTOT;
    float mm[NSPLIT], ll[NSPLIT];
    #pragma unroll
    for (int s = 0; s < NSPLIT; s++) {
        int pidx = (h*NSPLIT + s)*LTOT + r;
        mm[s] = g_pm[pidx]; ll[s] = g_pl[pidx];
    }
    float M = fmaxf(fmaxf(mm[0], mm[1]), fmaxf(mm[2], mm[3]));
    float e[NSPLIT]; float denom = 0.f;
    #pragma unroll
    for (int s = 0; s < NSPLIT; s++) { e[s] = __expf(mm[s] - M); denom += ll[s]*e[s]; }
    float4 acc = make_float4(0.f, 0.f, 0.f, 0.f);
    #pragma unroll
    for (int s = 0; s < NSPLIT; s++) {
        float4 v = *(const float4*)(g_po + (size_t)((h*NSPLIT + s)*LTOT + r)*DHEAD + f4*4);
        acc.x += v.x*e[s]; acc.y += v.y*e[s]; acc.z += v.z*e[s]; acc.w += v.w*e[s];
    }
    float inv = 1.f / denom;
    *(float4*)(g_og + (size_t)rowf*DHEAD + f4*4) =
        make_float4(acc.x*inv, acc.y*inv, acc.z*inv, acc.w*inv);
}

// ---------------- kernel 5: overlap-average gather + proj conv + residual ----------------
// grid = 1600 (pixels), block = 64 (channels)
__global__ void final_kernel(const float* __restrict__ x,
                             const float* __restrict__ Wp, const float* __restrict__ bp,
                             const float* __restrict__ pa_p, float* __restrict__ out) {
    __shared__ __align__(16) float sg[64];
    int p = blockIdx.x;
    int y = p / HW, xq = p % HW;
    int yp = y + 1, xp = xq + 1;
    int c = threadIdx.x;
    int h = c >> 5, dd = c & 31;

    int sylo = yp - 3; if (sylo < 0) sylo = 0; sylo += (sylo & 1);
    int syhi = yp > 38 ? 38 : yp;  syhi -= (syhi & 1);
    int sxlo = xp - 3; if (sxlo < 0) sxlo = 0; sxlo += (sxlo & 1);
    int sxhi = xp > 38 ? 38 : xp;  sxhi -= (sxhi & 1);

    float acc = 0.f; int cnt = 0;
    for (int sy = sylo; sy <= syhi; sy += 2)
        for (int sx = sxlo; sx <= sxhi; sx += 2) {
            int ty = yp - sy, tx = xp - sx;
            int lw = ((sy >> 1)*NH + (sx >> 1))*NTOK + ty*4 + tx;
            acc += g_og[(h*LTOT + lw)*DHEAD + dd];
            cnt++;
        }
    sg[c] = acc / ((float)cnt + 1e-6f);
    __syncthreads();

    float a = 2.f / (1.f + __expf(-(*pa_p)));
    float pr = bp[c];
    const float4* wrow = (const float4*)(Wp + c*64);
    #pragma unroll
    for (int i = 0; i < 16; i++) {
        float4 w = wrow[i];
        float4 g = *(const float4*)(sg + i*4);
        pr += w.x*g.x + w.y*g.y + w.z*g.z + w.w*g.w;
    }
    int oi = c*1600 + y*HW + xq;
    out[oi] = x[oi] + a*pr;
}

// ---------------- launcher ----------------
extern "C" void kernel_launch(void* const* d_in, const int* in_sizes, int n_in,
                              void* d_out, int out_size) {
    const float* x     = (const float*)d_in[0];
    const float* z     = (const float*)d_in[1];
    const float* Wqkv  = (const float*)d_in[2];
    const float* bqkv  = (const float*)d_in[3];
    const float* Wqkz  = (const float*)d_in[4];
    const float* bqkz  = (const float*)d_in[5];
    const float* Wproj = (const float*)d_in[6];
    const float* bproj = (const float*)d_in[7];
    const float* pa    = (const float*)d_in[8];
    const float* pbeta = (const float*)d_in[9];
    float* out = (float*)d_out;

    proj_kernel<<<HP, 320>>>(x, z, Wqkv, bqkv, Wqkz, bqkz);
    local_attn_kernel<<<dim3(NWIN, HEADS), 256>>>(pbeta);
    flash_kernel<<<dim3(LTOT/64, NSPLIT, HEADS), 64>>>();
    merge_kernel<<<LTOT*HEADS*8/256, 256>>>();
    final_kernel<<<HW*HW, 64>>>(x, Wproj, bproj, pa, out);
}

// round 2
// speedup vs baseline: 1.2107x; 1.2107x over previous
#include <cuda_runtime.h>
#include <math.h>

// ---------------- problem constants ----------------
#define HEADS 2
#define DHEAD 32
#define HW    40
#define HP    42           // padded 42x42
#define NPIX  (HP*HP)      // 1764
#define NH    20
#define NWIN  400
#define NTOK  16
#define LTOT  6400         // NWIN*NTOK
#define NSPLIT 8
#define KSEG  800          // LTOT/NSPLIT
#define KCHUNK 160
#define SCALE 0.17677669529663687f  // 1/sqrt(32)
#define QSCL  (0.17677669529663687f * 1.4426950408889634f)  // SCALE * log2(e)

// ---------------- scratch (__device__ globals; no allocs allowed) ----------------
__device__ float g_qx[NPIX*64];
__device__ float g_kx[NPIX*64];
__device__ float g_vx[NPIX*64];
__device__ float g_qz[NPIX*64];
__device__ float g_kz[NPIX*64];
__device__ float g_qg[HEADS*LTOT*DHEAD];        // local-attn output == global Q=K=V
__device__ float g_og[HEADS*LTOT*DHEAD];        // global-attn output (normalized)
__device__ float g_po[HEADS*NSPLIT*LTOT*DHEAD]; // partial (unnormalized) O
__device__ float g_pl[HEADS*NSPLIT*LTOT];       // partial row expsum

// ---------------- packed f32x2 helpers (Blackwell: 2x fp32 throughput) ----------------
static __device__ __forceinline__ float2 ffma2(float2 a, float2 b, float2 c) {
    float2 r;
    asm("fma.rn.f32x2 %0, %1, %2, %3;"
        : "=l"(reinterpret_cast<unsigned long long&>(r))
        : "l"(reinterpret_cast<unsigned long long&>(a)),
          "l"(reinterpret_cast<unsigned long long&>(b)),
          "l"(reinterpret_cast<unsigned long long&>(c)));
    return r;
}
static __device__ __forceinline__ float2 fmul2(float2 a, float2 b) {
    float2 r;
    asm("mul.rn.f32x2 %0, %1, %2;"
        : "=l"(reinterpret_cast<unsigned long long&>(r))
        : "l"(reinterpret_cast<unsigned long long&>(a)),
          "l"(reinterpret_cast<unsigned long long&>(b)));
    return r;
}
static __device__ __forceinline__ float2 fadd2(float2 a, float2 b) {
    float2 r;
    asm("add.rn.f32x2 %0, %1, %2;"
        : "=l"(reinterpret_cast<unsigned long long&>(r))
        : "l"(reinterpret_cast<unsigned long long&>(a)),
          "l"(reinterpret_cast<unsigned long long&>(b)));
    return r;
}
static __device__ __forceinline__ float ex2f(float x) {
    float r;
    asm("ex2.approx.f32 %0, %1;" : "=f"(r) : "f"(x));
    return r;
}

static __device__ __forceinline__ int reflect40(int v) {
    // jnp.pad 'reflect' with pad 1: -1 -> 1, 40 -> 38
    return v < 0 ? -v : (v > 39 ? 78 - v : v);
}

// ---------------- kernel 1: conv1x1 projections with reflect pad ----------------
// grid = 42 (one padded row), block = 320 (one thread per output channel of 192+128)
__global__ void proj_kernel(const float* __restrict__ x, const float* __restrict__ z,
                            const float* __restrict__ Wx, const float* __restrict__ bx,
                            const float* __restrict__ Wz, const float* __restrict__ bz) {
    __shared__ __align__(16) float xs[HP*68];
    __shared__ __align__(16) float zs[HP*68];
    int yp = blockIdx.x;
    int ys = reflect40(yp - 1);
    for (int idx = threadIdx.x; idx < HP*64; idx += blockDim.x) {
        int c = idx / HP, xp = idx % HP;
        int xsrc = reflect40(xp - 1);
        int src = c*1600 + ys*HW + xsrc;
        xs[xp*68 + c] = x[src];
        zs[xp*68 + c] = z[src];
    }
    __syncthreads();

    int oc = threadIdx.x;            // 0..319
    const float* wrow; float bias; float* dst; int cout; const float* sm;
    if (oc < 192) {
        wrow = Wx + oc*64; bias = bx[oc];
        int t = oc >> 6; cout = oc & 63;
        dst = (t == 0) ? g_qx : (t == 1 ? g_kx : g_vx);
        sm = xs;
    } else {
        int ozc = oc - 192;
        wrow = Wz + ozc*64; bias = bz[ozc];
        cout = ozc & 63;
        dst = (ozc < 64) ? g_qz : g_kz;
        sm = zs;
    }
    float4 wr[16];
    #pragma unroll
    for (int i = 0; i < 16; i++) wr[i] = ((const float4*)wrow)[i];

    for (int xp = 0; xp < HP; xp++) {
        float acc = bias;
        #pragma unroll
        for (int i = 0; i < 16; i++) {
            float4 v = *(const float4*)(sm + xp*68 + i*4);
            acc += wr[i].x*v.x + wr[i].y*v.y + wr[i].z*v.z + wr[i].w*v.w;
        }
        dst[(yp*HP + xp)*64 + cout] = acc;
    }
}

// ---------------- kernel 2: local 16x16 window attention ----------------
// grid = (400, 2) = (window, head), block = 256 = (i,j)
__global__ void local_attn_kernel(const float* __restrict__ pbeta_p) {
    __shared__ float sq[16*33], sk[16*33], sv[16*33], sqz[16*33], skz[16*33];
    __shared__ float sA[16*17];
    int win = blockIdx.x, h = blockIdx.y;
    int sy = (win / NH) * 2, sx = (win % NH) * 2;
    int tid = threadIdx.x;

    float* tiles[5] = {sq, sk, sv, sqz, skz};
    const float* gsrc[5] = {g_qx, g_kx, g_vx, g_qz, g_kz};
    for (int idx = tid; idx < 640; idx += 256) {
        int t = idx >> 7, rem = idx & 127, tok = rem >> 3, f4 = rem & 7;
        int ty = tok >> 2, tx = tok & 3;
        int pix = (sy + ty)*HP + (sx + tx);
        float4 v = *(const float4*)(gsrc[t] + pix*64 + h*DHEAD + f4*4);
        float* s = tiles[t];
        int so = tok*33 + f4*4;
        s[so] = v.x; s[so+1] = v.y; s[so+2] = v.z; s[so+3] = v.w;
    }
    __syncthreads();

    float pb = *pbeta_p;
    float beta = fmaxf(pb, 0.f) + log1pf(__expf(-fabsf(pb))) + 1e-6f;

    int i = tid >> 4, j = tid & 15;
    float dx = 0.f, dz = 0.f;
    #pragma unroll
    for (int dd = 0; dd < 32; dd++) {
        dx += sq[i*33+dd]  * sk[j*33+dd];
        dz += sqz[i*33+dd] * skz[j*33+dd];
    }
    float s = SCALE * (dx + beta*dz);
    float mx = s;
    #pragma unroll
    for (int off = 8; off; off >>= 1) mx = fmaxf(mx, __shfl_xor_sync(0xffffffffu, mx, off, 16));
    float p = __expf(s - mx);
    float sum = p;
    #pragma unroll
    for (int off = 8; off; off >>= 1) sum += __shfl_xor_sync(0xffffffffu, sum, off, 16);
    sA[i*17 + j] = p / sum;
    __syncthreads();

    #pragma unroll
    for (int pair = 0; pair < 2; pair++) {
        int idx = tid + pair*256;
        int ii = idx >> 5, dd = idx & 31;
        float acc = 0.f;
        #pragma unroll
        for (int jj = 0; jj < 16; jj++) acc += sA[ii*17+jj] * sv[jj*33+dd];
        g_qg[h*(LTOT*DHEAD) + (win*16 + ii)*DHEAD + dd] = acc;
    }
}

// ---------------- kernel 3: global flash attention (Q=K=V=qg), key-split x8 ----------------
// Branch-free: logits are bounded (|s*log2e| << 128), so no running max is
// needed; partials are plain (sum exp, sum exp*k) merged by summation.
// grid = (100, 8, 2) = (qtile of 64 rows, key split, head), block = 64 (1 thread/row)
__global__ void __launch_bounds__(64, 8) flash_kernel() {
    __shared__ __align__(16) float ks[KCHUNK*DHEAD];
    int tid = threadIdx.x;
    int row = blockIdx.x*64 + tid;
    int sp  = blockIdx.y;
    int h   = blockIdx.z;
    const float* qbase = g_qg + h*(LTOT*DHEAD);

    // q pre-scaled by SCALE*log2e so p = ex2(q.k) directly
    float2 q2[16];
    {
        const float4* qp = (const float4*)(qbase + row*DHEAD);
        #pragma unroll
        for (int i = 0; i < 8; i++) {
            float4 v = qp[i];
            q2[2*i]   = make_float2(v.x*QSCL, v.y*QSCL);
            q2[2*i+1] = make_float2(v.z*QSCL, v.w*QSCL);
        }
    }
    float l = 0.f;
    float2 o2[16];
    #pragma unroll
    for (int i = 0; i < 16; i++) o2[i] = make_float2(0.f, 0.f);

    const float4* gq4 = (const float4*)qbase;
    int k0 = sp * KSEG;
    for (int c = 0; c < KSEG/KCHUNK; c++) {
        int kstart = k0 + c*KCHUNK;
        float4* s4 = (float4*)ks;
        for (int idx = tid; idx < KCHUNK*8; idx += 64) s4[idx] = gq4[kstart*8 + idx];
        __syncthreads();

        #pragma unroll 2
        for (int j = 0; j < KCHUNK; j++) {
            const float4* kr4 = (const float4*)(ks + j*DHEAD);
            float2 kk[16];
            #pragma unroll
            for (int t = 0; t < 8; t++) {
                float4 v = kr4[t];
                kk[2*t]   = make_float2(v.x, v.y);
                kk[2*t+1] = make_float2(v.z, v.w);
            }
            float2 a0 = fmul2(q2[0], kk[0]);
            float2 a1 = fmul2(q2[1], kk[1]);
            float2 a2 = fmul2(q2[2], kk[2]);
            float2 a3 = fmul2(q2[3], kk[3]);
            #pragma unroll
            for (int t = 4; t < 16; t += 4) {
                a0 = ffma2(q2[t],   kk[t],   a0);
                a1 = ffma2(q2[t+1], kk[t+1], a1);
                a2 = ffma2(q2[t+2], kk[t+2], a2);
                a3 = ffma2(q2[t+3], kk[t+3], a3);
            }
            a0 = fadd2(a0, a1);
            a2 = fadd2(a2, a3);
            a0 = fadd2(a0, a2);
            float p = ex2f(a0.x + a0.y);
            l += p;
            float2 p2 = make_float2(p, p);
            #pragma unroll
            for (int t = 0; t < 16; t++) o2[t] = ffma2(p2, kk[t], o2[t]);
        }
        __syncthreads();
    }

    int pidx = (h*NSPLIT + sp)*LTOT + row;
    g_pl[pidx] = l;
    float4* po4 = (float4*)(g_po + (size_t)pidx*DHEAD);
    #pragma unroll
    for (int i = 0; i < 8; i++)
        po4[i] = make_float4(o2[2*i].x, o2[2*i].y, o2[2*i+1].x, o2[2*i+1].y);
}

// ---------------- kernel 4: merge key splits (plain sum + normalize) ----------------
// one thread per (row, float4-of-d); 12800 rows * 8 float4 = 102400 threads
__global__ void merge_kernel() {
    int t = blockIdx.x*256 + threadIdx.x;
    int rowf = t >> 3, f4 = t & 7;
    int h = rowf / LTOT, r = rowf % LTOT;
    float l = 0.f;
    #pragma unroll
    for (int s = 0; s < NSPLIT; s++) l += g_pl[(h*NSPLIT + s)*LTOT + r];
    float4 acc = make_float4(0.f, 0.f, 0.f, 0.f);
    #pragma unroll
    for (int s = 0; s < NSPLIT; s++) {
        float4 v = *(const float4*)(g_po + (size_t)((h*NSPLIT + s)*LTOT + r)*DHEAD + f4*4);
        acc.x += v.x; acc.y += v.y; acc.z += v.z; acc.w += v.w;
    }
    float inv = 1.f / l;
    *(float4*)(g_og + (size_t)rowf*DHEAD + f4*4) =
        make_float4(acc.x*inv, acc.y*inv, acc.z*inv, acc.w*inv);
}

// ---------------- kernel 5: overlap-average gather + proj conv + residual ----------------
// grid = 1600 (pixels), block = 64 (channels)
__global__ void final_kernel(const float* __restrict__ x,
                             const float* __restrict__ Wp, const float* __restrict__ bp,
                             const float* __restrict__ pa_p, float* __restrict__ out) {
    __shared__ __align__(16) float sg[64];
    int p = blockIdx.x;
    int y = p / HW, xq = p % HW;
    int yp = y + 1, xp = xq + 1;
    int c = threadIdx.x;
    int h = c >> 5, dd = c & 31;

    int sylo = yp - 3; if (sylo < 0) sylo = 0; sylo += (sylo & 1);
    int syhi = yp > 38 ? 38 : yp;  syhi -= (syhi & 1);
    int sxlo = xp - 3; if (sxlo < 0) sxlo = 0; sxlo += (sxlo & 1);
    int sxhi = xp > 38 ? 38 : xp;  sxhi -= (sxhi & 1);

    float acc = 0.f; int cnt = 0;
    for (int sy = sylo; sy <= syhi; sy += 2)
        for (int sx = sxlo; sx <= sxhi; sx += 2) {
            int ty = yp - sy, tx = xp - sx;
            int lw = ((sy >> 1)*NH + (sx >> 1))*NTOK + ty*4 + tx;
            acc += g_og[(h*LTOT + lw)*DHEAD + dd];
            cnt++;
        }
    sg[c] = acc / ((float)cnt + 1e-6f);
    __syncthreads();

    float a = 2.f / (1.f + __expf(-(*pa_p)));
    float pr = bp[c];
    const float4* wrow = (const float4*)(Wp + c*64);
    #pragma unroll
    for (int i = 0; i < 16; i++) {
        float4 w = wrow[i];
        float4 g = *(const float4*)(sg + i*4);
        pr += w.x*g.x + w.y*g.y + w.z*g.z + w.w*g.w;
    }
    int oi = c*1600 + y*HW + xq;
    out[oi] = x[oi] + a*pr;
}

// ---------------- launcher ----------------
extern "C" void kernel_launch(void* const* d_in, const int* in_sizes, int n_in,
                              void* d_out, int out_size) {
    const float* x     = (const float*)d_in[0];
    const float* z     = (const float*)d_in[1];
    const float* Wqkv  = (const float*)d_in[2];
    const float* bqkv  = (const float*)d_in[3];
    const float* Wqkz  = (const float*)d_in[4];
    const float* bqkz  = (const float*)d_in[5];
    const float* Wproj = (const float*)d_in[6];
    const float* bproj = (const float*)d_in[7];
    const float* pa    = (const float*)d_in[8];
    const float* pbeta = (const float*)d_in[9];
    float* out = (float*)d_out;

    proj_kernel<<<HP, 320>>>(x, z, Wqkv, bqkv, Wqkz, bqkz);
    local_attn_kernel<<<dim3(NWIN, HEADS), 256>>>(pbeta);
    flash_kernel<<<dim3(LTOT/64, NSPLIT, HEADS), 64>>>();
    merge_kernel<<<LTOT*HEADS*8/256, 256>>>();
    final_kernel<<<HW*HW, 64>>>(x, Wproj, bproj, pa, out);
}

// round 5
// speedup vs baseline: 2.1399x; 1.7674x over previous
#include <cuda_runtime.h>
#include <cuda_bf16.h>
#include <cstdint>
#include <math.h>

// ---------------- problem constants ----------------
#define HEADS 2
#define DHEAD 32
#define HW    40
#define HP    42
#define NPIX  (HP*HP)
#define NH    20
#define NWIN  400
#define NTOK  16
#define LTOT  6400
#define SCALE 0.17677669529663687f
#define QSCL  (0.17677669529663687f * 1.4426950408889634f)  // SCALE * log2(e)

// flash tiling (mma.sync path)
#define NSPLIT 2
#define KSEG   3200        // keys per split
#define KT     64          // keys per smem tile
#define NIT    (KSEG/KT)   // 50
// smem byte offsets within one buffer
#define B_KH   0           // 64 keys x 80B (64B data + 16 pad)
#define B_KL   5120
#define B_VTH  10240       // 32 dims x 144B (128B data + 16 pad)
#define B_VTL  14848
#define BUFB   19456

// ---------------- scratch ----------------
__device__ float g_qx[NPIX*64];
__device__ float g_kx[NPIX*64];
__device__ float g_vx[NPIX*64];
__device__ float g_qz[NPIX*64];
__device__ float g_kz[NPIX*64];
__device__ float g_qg[HEADS*LTOT*DHEAD];            // local-attn out == global QKV (fp32)
__device__ float g_og[HEADS*LTOT*DHEAD];            // global-attn out (normalized)
__device__ __align__(256) __nv_bfloat16 g_qs[HEADS*LTOT*64];  // [row][qh32|ql32], pre-scaled
__device__ __align__(256) __nv_bfloat16 g_ks[HEADS*LTOT*64];  // [row][kh32|kl32]
__device__ __align__(256) __nv_bfloat16 g_vt[HEADS*2*DHEAD*LTOT]; // [h][split][d][key]
__device__ float g_po[HEADS*NSPLIT*LTOT*DHEAD];     // partial unnormalized O
__device__ float g_pl[HEADS*NSPLIT*LTOT];           // partial expsum

// ---------------- helpers ----------------
static __device__ __forceinline__ uint32_t smem_u32(const void* p) {
    uint32_t a;
    asm("{ .reg .u64 t; cvta.to.shared.u64 t, %1; cvt.u32.u64 %0, t; }" : "=r"(a) : "l"(p));
    return a;
}
static __device__ __forceinline__ float ex2f(float x) {
    float r; asm("ex2.approx.f32 %0, %1;" : "=f"(r) : "f"(x)); return r;
}
static __device__ __forceinline__ uint32_t packbf(float lo, float hi) {
    uint32_t r; asm("cvt.rn.bf16x2.f32 %0, %1, %2;" : "=r"(r) : "f"(hi), "f"(lo)); return r;
}
// mma.sync m16n8k16 bf16 (sm_80+ baseline PTX; runs on Blackwell tensor pipe)
static __device__ __forceinline__ void mma_bf16(float* d, const uint32_t* a, uint32_t b0, uint32_t b1) {
    asm volatile("mma.sync.aligned.m16n8k16.row.col.f32.bf16.bf16.f32 "
        "{%0,%1,%2,%3}, {%4,%5,%6,%7}, {%8,%9}, {%0,%1,%2,%3};"
        : "+f"(d[0]), "+f"(d[1]), "+f"(d[2]), "+f"(d[3])
        : "r"(a[0]), "r"(a[1]), "r"(a[2]), "r"(a[3]), "r"(b0), "r"(b1));
}
static __device__ __forceinline__ void cp_async16(uint32_t dst, const void* src) {
    asm volatile("cp.async.cg.shared.global [%0], [%1], 16;" :: "r"(dst), "l"(src));
}
#define CP_COMMIT() asm volatile("cp.async.commit_group;" ::: "memory")

static __device__ __forceinline__ int reflect40(int v) {
    return v < 0 ? -v : (v > 39 ? 78 - v : v);
}

// ---------------- kernel 1: conv1x1 projections with reflect pad ----------------
__global__ void proj_kernel(const float* __restrict__ x, const float* __restrict__ z,
                            const float* __restrict__ Wx, const float* __restrict__ bx,
                            const float* __restrict__ Wz, const float* __restrict__ bz) {
    __shared__ __align__(16) float xs[HP*68];
    __shared__ __align__(16) float zs[HP*68];
    int yp = blockIdx.x;
    int ys = reflect40(yp - 1);
    for (int idx = threadIdx.x; idx < HP*64; idx += blockDim.x) {
        int c = idx / HP, xp = idx % HP;
        int xsrc = reflect40(xp - 1);
        int src = c*1600 + ys*HW + xsrc;
        xs[xp*68 + c] = x[src];
        zs[xp*68 + c] = z[src];
    }
    __syncthreads();
    int oc = threadIdx.x;
    const float* wrow; float bias; float* dst; int cout; const float* sm;
    if (oc < 192) {
        wrow = Wx + oc*64; bias = bx[oc];
        int t = oc >> 6; cout = oc & 63;
        dst = (t == 0) ? g_qx : (t == 1 ? g_kx : g_vx);
        sm = xs;
    } else {
        int ozc = oc - 192;
        wrow = Wz + ozc*64; bias = bz[ozc];
        cout = ozc & 63;
        dst = (ozc < 64) ? g_qz : g_kz;
        sm = zs;
    }
    float4 wr[16];
    #pragma unroll
    for (int i = 0; i < 16; i++) wr[i] = ((const float4*)wrow)[i];
    for (int xp = 0; xp < HP; xp++) {
        float acc = bias;
        #pragma unroll
        for (int i = 0; i < 16; i++) {
            float4 v = *(const float4*)(sm + xp*68 + i*4);
            acc += wr[i].x*v.x + wr[i].y*v.y + wr[i].z*v.z + wr[i].w*v.w;
        }
        dst[(yp*HP + xp)*64 + cout] = acc;
    }
}

// ---------------- kernel 2: local 16x16 window attention ----------------
__global__ void local_attn_kernel(const float* __restrict__ pbeta_p) {
    __shared__ float sq[16*33], sk[16*33], sv[16*33], sqz[16*33], skz[16*33];
    __shared__ float sA[16*17];
    int win = blockIdx.x, h = blockIdx.y;
    int sy = (win / NH) * 2, sx = (win % NH) * 2;
    int tid = threadIdx.x;
    float* tiles[5] = {sq, sk, sv, sqz, skz};
    const float* gsrc[5] = {g_qx, g_kx, g_vx, g_qz, g_kz};
    for (int idx = tid; idx < 640; idx += 256) {
        int t = idx >> 7, rem = idx & 127, tok = rem >> 3, f4 = rem & 7;
        int ty = tok >> 2, tx = tok & 3;
        int pix = (sy + ty)*HP + (sx + tx);
        float4 v = *(const float4*)(gsrc[t] + pix*64 + h*DHEAD + f4*4);
        float* s = tiles[t];
        int so = tok*33 + f4*4;
        s[so] = v.x; s[so+1] = v.y; s[so+2] = v.z; s[so+3] = v.w;
    }
    __syncthreads();
    float pb = *pbeta_p;
    float beta = fmaxf(pb, 0.f) + log1pf(__expf(-fabsf(pb))) + 1e-6f;
    int i = tid >> 4, j = tid & 15;
    float dx = 0.f, dz = 0.f;
    #pragma unroll
    for (int dd = 0; dd < 32; dd++) {
        dx += sq[i*33+dd]  * sk[j*33+dd];
        dz += sqz[i*33+dd] * skz[j*33+dd];
    }
    float s = SCALE * (dx + beta*dz);
    float mx = s;
    #pragma unroll
    for (int off = 8; off; off >>= 1) mx = fmaxf(mx, __shfl_xor_sync(0xffffffffu, mx, off, 16));
    float p = __expf(s - mx);
    float sum = p;
    #pragma unroll
    for (int off = 8; off; off >>= 1) sum += __shfl_xor_sync(0xffffffffu, sum, off, 16);
    sA[i*17 + j] = p / sum;
    __syncthreads();
    #pragma unroll
    for (int pair = 0; pair < 2; pair++) {
        int idx = tid + pair*256;
        int ii = idx >> 5, dd = idx & 31;
        float acc = 0.f;
        #pragma unroll
        for (int jj = 0; jj < 16; jj++) acc += sA[ii*17+jj] * sv[jj*33+dd];
        g_qg[h*(LTOT*DHEAD) + (win*16 + ii)*DHEAD + dd] = acc;
    }
}

// ---------------- kernel 2.5: split fp32 -> bf16 hi/lo (Q scaled, K, V^T) ----------------
__global__ void prep_kernel() {
    int g = blockIdx.x*128 + threadIdx.x;     // 0..12799
    int h = g / LTOT, r = g % LTOT;
    const float* q = g_qg + (size_t)g*DHEAD;
    __nv_bfloat16* qd = g_qs + (size_t)g*64;
    __nv_bfloat16* kd = g_ks + (size_t)g*64;
    __nv_bfloat16* vth = g_vt + ((size_t)(h*2+0)*DHEAD)*LTOT + r;
    __nv_bfloat16* vtl = g_vt + ((size_t)(h*2+1)*DHEAD)*LTOT + r;
    #pragma unroll
    for (int d = 0; d < DHEAD; d++) {
        float kv = q[d];
        __nv_bfloat16 kh = __float2bfloat16_rn(kv);
        __nv_bfloat16 kl = __float2bfloat16_rn(kv - __bfloat162float(kh));
        kd[d] = kh; kd[32+d] = kl;
        vth[d*LTOT] = kh; vtl[d*LTOT] = kl;
        float qv = kv * QSCL;
        __nv_bfloat16 qh = __float2bfloat16_rn(qv);
        qd[d] = qh; qd[32+d] = __float2bfloat16_rn(qv - __bfloat162float(qh));
    }
}

// ---------------- kernel 3: flash attention on mma.sync bf16 (split hi/lo) ----------------
// grid = (50 qtiles, 2 key-splits, 2 heads), block = 256 (8 warps x 16 rows)
__global__ void __launch_bounds__(256, 2) flashmma_kernel() {
    __shared__ __align__(16) char smem[2*BUFB];
    const int tid = threadIdx.x, w = tid >> 5, lane = tid & 31;
    const int tg = lane >> 2, tc = lane & 3;            // groupID, threadInGroup
    const int qt = blockIdx.x, sp = blockIdx.y, h = blockIdx.z;
    const int k0 = sp * KSEG;
    const uint32_t sbase = smem_u32(smem);

    // ---- cooperative double-buffered tile loads (cp.async) ----
    auto load_tiles = [&](int t, int buf) {
        uint32_t db = sbase + buf*BUFB;
        const char* kg = (const char*)(g_ks + ((size_t)h*LTOT + k0 + t*KT)*64);
        #pragma unroll
        for (int j = 0; j < 2; j++) {
            int i = tid + j*256;                        // 0..511
            int r = i >> 3, half = (i >> 2) & 1, c = i & 3;
            cp_async16(db + (half ? B_KL : B_KH) + r*80 + c*16,
                       kg + r*128 + half*64 + c*16);
        }
        #pragma unroll
        for (int j = 0; j < 2; j++) {
            int i = tid + j*256;                        // sp2 x d32 x kg8
            int vsp = i >> 8, rem = i & 255, d = rem >> 3, kgi = rem & 7;
            const char* src = (const char*)(g_vt + ((size_t)(h*2+vsp)*DHEAD + d)*LTOT + k0 + t*KT) + kgi*16;
            cp_async16(db + (vsp ? B_VTL : B_VTH) + d*144 + kgi*16, src);
        }
    };

    load_tiles(0, 0);
    CP_COMMIT();

    // ---- Q fragments (A of m16n8k16), rows w*16 .. w*16+15, hi/lo splits ----
    uint32_t qh[2][4], ql[2][4];
    {
        const uint32_t* qb = (const uint32_t*)g_qs + ((size_t)h*LTOT + qt*128 + w*16)*32;
        #pragma unroll
        for (int ks = 0; ks < 2; ks++) {
            int ca = ks*8 + tc;
            qh[ks][0] = qb[tg*32     + ca];
            qh[ks][1] = qb[(tg+8)*32 + ca];
            qh[ks][2] = qb[tg*32     + ca + 4];
            qh[ks][3] = qb[(tg+8)*32 + ca + 4];
            ql[ks][0] = qb[tg*32     + 16 + ca];
            ql[ks][1] = qb[(tg+8)*32 + 16 + ca];
            ql[ks][2] = qb[tg*32     + 16 + ca + 4];
            ql[ks][3] = qb[(tg+8)*32 + 16 + ca + 4];
        }
    }

    float oacc[4][4];
    #pragma unroll
    for (int i = 0; i < 4; i++)
        #pragma unroll
        for (int j = 0; j < 4; j++) oacc[i][j] = 0.f;
    float lr = 0.f, lr8 = 0.f;

    for (int t = 0; t < NIT; t++) {
        if (t + 1 < NIT) { load_tiles(t + 1, (t + 1) & 1); CP_COMMIT(); }
        if (t + 1 < NIT) asm volatile("cp.async.wait_group 1;" ::: "memory");
        else             asm volatile("cp.async.wait_group 0;" ::: "memory");
        __syncthreads();

        const uint32_t* KH  = (const uint32_t*)(smem + (t & 1)*BUFB + B_KH);
        const uint32_t* KL  = (const uint32_t*)(smem + (t & 1)*BUFB + B_KL);
        const uint32_t* VTH = (const uint32_t*)(smem + (t & 1)*BUFB + B_VTH);
        const uint32_t* VTL = (const uint32_t*)(smem + (t & 1)*BUFB + B_VTL);

        // ---- S = Q K^T : 8 ntiles of 8 keys, fp32 accum ----
        float sacc[8][4];
        #pragma unroll
        for (int nt = 0; nt < 8; nt++) {
            sacc[nt][0] = sacc[nt][1] = sacc[nt][2] = sacc[nt][3] = 0.f;
            #pragma unroll
            for (int ks = 0; ks < 2; ks++) {
                int ad = (nt*8 + tg)*20 + ks*8 + tc;
                uint32_t bh0 = KH[ad], bh1 = KH[ad+4];
                uint32_t bl0 = KL[ad], bl1 = KL[ad+4];
                mma_bf16(sacc[nt], qh[ks], bh0, bh1);
                mma_bf16(sacc[nt], qh[ks], bl0, bl1);
                mma_bf16(sacc[nt], ql[ks], bh0, bh1);
            }
        }

        // ---- epilogue: p = 2^s; pack into A fragments (hi/lo split) ----
        uint32_t pha[4][4], pla[4][4];
        #pragma unroll
        for (int kt = 0; kt < 4; kt++) {
            float p0 = ex2f(sacc[2*kt][0]),   p1 = ex2f(sacc[2*kt][1]);
            float p2 = ex2f(sacc[2*kt][2]),   p3 = ex2f(sacc[2*kt][3]);
            float p4 = ex2f(sacc[2*kt+1][0]), p5 = ex2f(sacc[2*kt+1][1]);
            float p6 = ex2f(sacc[2*kt+1][2]), p7 = ex2f(sacc[2*kt+1][3]);
            lr  += (p0 + p1) + (p4 + p5);
            lr8 += (p2 + p3) + (p6 + p7);
            uint32_t u0 = packbf(p0, p1), u1 = packbf(p2, p3);
            uint32_t u2 = packbf(p4, p5), u3 = packbf(p6, p7);
            pha[kt][0] = u0; pha[kt][1] = u1; pha[kt][2] = u2; pha[kt][3] = u3;
            pla[kt][0] = packbf(p0 - __uint_as_float(u0 << 16), p1 - __uint_as_float(u0 & 0xffff0000u));
            pla[kt][1] = packbf(p2 - __uint_as_float(u1 << 16), p3 - __uint_as_float(u1 & 0xffff0000u));
            pla[kt][2] = packbf(p4 - __uint_as_float(u2 << 16), p5 - __uint_as_float(u2 & 0xffff0000u));
            pla[kt][3] = packbf(p6 - __uint_as_float(u3 << 16), p7 - __uint_as_float(u3 & 0xffff0000u));
        }

        // ---- O += P V ----
        #pragma unroll
        for (int dt = 0; dt < 4; dt++) {
            #pragma unroll
            for (int kt = 0; kt < 4; kt++) {
                int ad = (dt*8 + tg)*36 + kt*8 + tc;
                uint32_t vh0 = VTH[ad], vh1 = VTH[ad+4];
                uint32_t vl0 = VTL[ad], vl1 = VTL[ad+4];
                mma_bf16(oacc[dt], pha[kt], vh0, vh1);
                mma_bf16(oacc[dt], pha[kt], vl0, vl1);
                mma_bf16(oacc[dt], pla[kt], vh0, vh1);
            }
        }
        __syncthreads();
    }

    // ---- reduce l across the quad and store partials ----
    lr  += __shfl_xor_sync(0xffffffffu, lr, 1);
    lr  += __shfl_xor_sync(0xffffffffu, lr, 2);
    lr8 += __shfl_xor_sync(0xffffffffu, lr8, 1);
    lr8 += __shfl_xor_sync(0xffffffffu, lr8, 2);

    int rowa = qt*128 + w*16 + tg, rowb = rowa + 8;
    int pb = (h*NSPLIT + sp)*LTOT;
    if (tc == 0) { g_pl[pb + rowa] = lr; g_pl[pb + rowb] = lr8; }
    float2* pa = (float2*)(g_po + ((size_t)(pb + rowa))*DHEAD);
    float2* pbv = (float2*)(g_po + ((size_t)(pb + rowb))*DHEAD);
    #pragma unroll
    for (int dt = 0; dt < 4; dt++) {
        pa [dt*4 + tc] = make_float2(oacc[dt][0], oacc[dt][1]);
        pbv[dt*4 + tc] = make_float2(oacc[dt][2], oacc[dt][3]);
    }
}

// ---------------- kernel 4: merge key splits (plain sum + normalize) ----------------
__global__ void merge_kernel() {
    int t = blockIdx.x*256 + threadIdx.x;
    int rowf = t >> 3, f4 = t & 7;
    int h = rowf / LTOT, r = rowf % LTOT;
    float l = 0.f;
    #pragma unroll
    for (int s = 0; s < NSPLIT; s++) l += g_pl[(h*NSPLIT + s)*LTOT + r];
    float4 acc = make_float4(0.f, 0.f, 0.f, 0.f);
    #pragma unroll
    for (int s = 0; s < NSPLIT; s++) {
        float4 v = *(const float4*)(g_po + (size_t)((h*NSPLIT + s)*LTOT + r)*DHEAD + f4*4);
        acc.x += v.x; acc.y += v.y; acc.z += v.z; acc.w += v.w;
    }
    float inv = 1.f / l;
    *(float4*)(g_og + (size_t)rowf*DHEAD + f4*4) =
        make_float4(acc.x*inv, acc.y*inv, acc.z*inv, acc.w*inv);
}

// ---------------- kernel 5: overlap-average gather + proj conv + residual ----------------
__global__ void final_kernel(const float* __restrict__ x,
                             const float* __restrict__ Wp, const float* __restrict__ bp,
                             const float* __restrict__ pa_p, float* __restrict__ out) {
    __shared__ __align__(16) float sg[64];
    int p = blockIdx.x;
    int y = p / HW, xq = p % HW;
    int yp = y + 1, xp = xq + 1;
    int c = threadIdx.x;
    int h = c >> 5, dd = c & 31;
    int sylo = yp - 3; if (sylo < 0) sylo = 0; sylo += (sylo & 1);
    int syhi = yp > 38 ? 38 : yp;  syhi -= (syhi & 1);
    int sxlo = xp - 3; if (sxlo < 0) sxlo = 0; sxlo += (sxlo & 1);
    int sxhi = xp > 38 ? 38 : xp;  sxhi -= (sxhi & 1);
    float acc = 0.f; int cnt = 0;
    for (int sy = sylo; sy <= syhi; sy += 2)
        for (int sx = sxlo; sx <= sxhi; sx += 2) {
            int ty = yp - sy, tx = xp - sx;
            int lw = ((sy >> 1)*NH + (sx >> 1))*NTOK + ty*4 + tx;
            acc += g_og[(h*LTOT + lw)*DHEAD + dd];
            cnt++;
        }
    sg[c] = acc / ((float)cnt + 1e-6f);
    __syncthreads();
    float a = 2.f / (1.f + __expf(-(*pa_p)));
    float pr = bp[c];
    const float4* wrow = (const float4*)(Wp + c*64);
    #pragma unroll
    for (int i = 0; i < 16; i++) {
        float4 w = wrow[i];
        float4 g = *(const float4*)(sg + i*4);
        pr += w.x*g.x + w.y*g.y + w.z*g.z + w.w*g.w;
    }
    int oi = c*1600 + y*HW + xq;
    out[oi] = x[oi] + a*pr;
}

// ---------------- launcher ----------------
extern "C" void kernel_launch(void* const* d_in, const int* in_sizes, int n_in,
                              void* d_out, int out_size) {
    (void)in_sizes; (void)n_in; (void)out_size;
    const float* x     = (const float*)d_in[0];
    const float* z     = (const float*)d_in[1];
    const float* Wqkv  = (const float*)d_in[2];
    const float* bqkv  = (const float*)d_in[3];
    const float* Wqkz  = (const float*)d_in[4];
    const float* bqkz  = (const float*)d_in[5];
    const float* Wproj = (const float*)d_in[6];
    const float* bproj = (const float*)d_in[7];
    const float* pa    = (const float*)d_in[8];
    const float* pbeta = (const float*)d_in[9];
    float* out = (float*)d_out;

    proj_kernel<<<HP, 320>>>(x, z, Wqkv, bqkv, Wqkz, bqkz);
    local_attn_kernel<<<dim3(NWIN, HEADS), 256>>>(pbeta);
    prep_kernel<<<100, 128>>>();
    flashmma_kernel<<<dim3(LTOT/128, NSPLIT, HEADS), 256>>>();
    merge_kernel<<<LTOT*HEADS*8/256, 256>>>();
    final_kernel<<<HW*HW, 64>>>(x, Wproj, bproj, pa, out);
}

// round 6
// speedup vs baseline: 2.7070x; 1.2650x over previous
#include <cuda_runtime.h>
#include <cuda_bf16.h>
#include <cstdint>
#include <math.h>

// ---------------- problem constants ----------------
#define HEADS 2
#define DHEAD 32
#define HW    40
#define HP    42
#define NPIX  (HP*HP)
#define NH    20
#define NWIN  400
#define NTOK  16
#define LTOT  6400
#define SCALE 0.17677669529663687f
#define QSCL  (0.17677669529663687f * 1.4426950408889634f)  // SCALE * log2(e)

// flash work decomposition (persistent balanced schedule)
#define KT        64          // keys per unit (smem tile)
#define UPR       100         // units per row-group (6400/64)
#define NRG       100         // row-groups: 2 heads x 50 q-tiles of 128 rows
#define UTOT      (NRG*UPR)   // 10000
#define G_BLOCKS  296         // exactly 2 blocks/SM x 148 SMs -> uniform 16 warps/SM
#define NSLOT     4           // max blocks intersecting one row-group (chunk >= 33)
// smem byte offsets within one buffer
#define B_KH   0              // 64 keys x 80B (64B data + 16 pad)
#define B_KL   5120
#define B_VTH  10240          // 32 dims x 144B (128B data + 16 pad)
#define B_VTL  14848
#define BUFB   19456

// ---------------- scratch ----------------
__device__ float g_qx[NPIX*64];
__device__ float g_kx[NPIX*64];
__device__ float g_vx[NPIX*64];
__device__ float g_qz[NPIX*64];
__device__ float g_kz[NPIX*64];
__device__ float g_qg[HEADS*LTOT*DHEAD];            // local-attn out == global QKV (fp32)
__device__ float g_og[HEADS*LTOT*DHEAD];            // global-attn out (normalized)
__device__ __align__(256) __nv_bfloat16 g_qs[HEADS*LTOT*64];  // [row][qh32|ql32], pre-scaled
__device__ __align__(256) __nv_bfloat16 g_ks[HEADS*LTOT*64];  // [row][kh32|kl32]
__device__ __align__(256) __nv_bfloat16 g_vt[HEADS*2*DHEAD*LTOT]; // [h][split][d][key]
__device__ float g_po[NRG*NSLOT*128*DHEAD];         // partial unnormalized O per (rg, slot)
__device__ float g_pl[NRG*NSLOT*128];               // partial expsum per (rg, slot)

// ---------------- helpers ----------------
static __device__ __forceinline__ uint32_t smem_u32(const void* p) {
    uint32_t a;
    asm("{ .reg .u64 t; cvta.to.shared.u64 t, %1; cvt.u32.u64 %0, t; }" : "=r"(a) : "l"(p));
    return a;
}
static __device__ __forceinline__ float ex2f(float x) {
    float r; asm("ex2.approx.f32 %0, %1;" : "=f"(r) : "f"(x)); return r;
}
static __device__ __forceinline__ uint32_t packbf(float lo, float hi) {
    uint32_t r; asm("cvt.rn.bf16x2.f32 %0, %1, %2;" : "=r"(r) : "f"(hi), "f"(lo)); return r;
}
// mma.sync m16n8k16 bf16 (sm_80+ baseline PTX; runs on Blackwell tensor pipe)
static __device__ __forceinline__ void mma_bf16(float* d, const uint32_t* a, uint32_t b0, uint32_t b1) {
    asm volatile("mma.sync.aligned.m16n8k16.row.col.f32.bf16.bf16.f32 "
        "{%0,%1,%2,%3}, {%4,%5,%6,%7}, {%8,%9}, {%0,%1,%2,%3};"
        : "+f"(d[0]), "+f"(d[1]), "+f"(d[2]), "+f"(d[3])
        : "r"(a[0]), "r"(a[1]), "r"(a[2]), "r"(a[3]), "r"(b0), "r"(b1));
}
static __device__ __forceinline__ void cp_async16(uint32_t dst, const void* src) {
    asm volatile("cp.async.cg.shared.global [%0], [%1], 16;" :: "r"(dst), "l"(src));
}
#define CP_COMMIT() asm volatile("cp.async.commit_group;" ::: "memory")

static __device__ __forceinline__ int reflect40(int v) {
    return v < 0 ? -v : (v > 39 ? 78 - v : v);
}

// ---------------- kernel 1: conv1x1 projections with reflect pad ----------------
__global__ void proj_kernel(const float* __restrict__ x, const float* __restrict__ z,
                            const float* __restrict__ Wx, const float* __restrict__ bx,
                            const float* __restrict__ Wz, const float* __restrict__ bz) {
    __shared__ __align__(16) float xs[HP*68];
    __shared__ __align__(16) float zs[HP*68];
    int yp = blockIdx.x;
    int ys = reflect40(yp - 1);
    for (int idx = threadIdx.x; idx < HP*64; idx += blockDim.x) {
        int c = idx / HP, xp = idx % HP;
        int xsrc = reflect40(xp - 1);
        int src = c*1600 + ys*HW + xsrc;
        xs[xp*68 + c] = x[src];
        zs[xp*68 + c] = z[src];
    }
    __syncthreads();
    int oc = threadIdx.x;
    const float* wrow; float bias; float* dst; int cout; const float* sm;
    if (oc < 192) {
        wrow = Wx + oc*64; bias = bx[oc];
        int t = oc >> 6; cout = oc & 63;
        dst = (t == 0) ? g_qx : (t == 1 ? g_kx : g_vx);
        sm = xs;
    } else {
        int ozc = oc - 192;
        wrow = Wz + ozc*64; bias = bz[ozc];
        cout = ozc & 63;
        dst = (ozc < 64) ? g_qz : g_kz;
        sm = zs;
    }
    float4 wr[16];
    #pragma unroll
    for (int i = 0; i < 16; i++) wr[i] = ((const float4*)wrow)[i];
    for (int xp = 0; xp < HP; xp++) {
        float acc = bias;
        #pragma unroll
        for (int i = 0; i < 16; i++) {
            float4 v = *(const float4*)(sm + xp*68 + i*4);
            acc += wr[i].x*v.x + wr[i].y*v.y + wr[i].z*v.z + wr[i].w*v.w;
        }
        dst[(yp*HP + xp)*64 + cout] = acc;
    }
}

// ---------------- kernel 2: local 16x16 window attention ----------------
__global__ void local_attn_kernel(const float* __restrict__ pbeta_p) {
    __shared__ float sq[16*33], sk[16*33], sv[16*33], sqz[16*33], skz[16*33];
    __shared__ float sA[16*17];
    int win = blockIdx.x, h = blockIdx.y;
    int sy = (win / NH) * 2, sx = (win % NH) * 2;
    int tid = threadIdx.x;
    float* tiles[5] = {sq, sk, sv, sqz, skz};
    const float* gsrc[5] = {g_qx, g_kx, g_vx, g_qz, g_kz};
    for (int idx = tid; idx < 640; idx += 256) {
        int t = idx >> 7, rem = idx & 127, tok = rem >> 3, f4 = rem & 7;
        int ty = tok >> 2, tx = tok & 3;
        int pix = (sy + ty)*HP + (sx + tx);
        float4 v = *(const float4*)(gsrc[t] + pix*64 + h*DHEAD + f4*4);
        float* s = tiles[t];
        int so = tok*33 + f4*4;
        s[so] = v.x; s[so+1] = v.y; s[so+2] = v.z; s[so+3] = v.w;
    }
    __syncthreads();
    float pb = *pbeta_p;
    float beta = fmaxf(pb, 0.f) + log1pf(__expf(-fabsf(pb))) + 1e-6f;
    int i = tid >> 4, j = tid & 15;
    float dx = 0.f, dz = 0.f;
    #pragma unroll
    for (int dd = 0; dd < 32; dd++) {
        dx += sq[i*33+dd]  * sk[j*33+dd];
        dz += sqz[i*33+dd] * skz[j*33+dd];
    }
    float s = SCALE * (dx + beta*dz);
    float mx = s;
    #pragma unroll
    for (int off = 8; off; off >>= 1) mx = fmaxf(mx, __shfl_xor_sync(0xffffffffu, mx, off, 16));
    float p = __expf(s - mx);
    float sum = p;
    #pragma unroll
    for (int off = 8; off; off >>= 1) sum += __shfl_xor_sync(0xffffffffu, sum, off, 16);
    sA[i*17 + j] = p / sum;
    __syncthreads();
    #pragma unroll
    for (int pair = 0; pair < 2; pair++) {
        int idx = tid + pair*256;
        int ii = idx >> 5, dd = idx & 31;
        float acc = 0.f;
        #pragma unroll
        for (int jj = 0; jj < 16; jj++) acc += sA[ii*17+jj] * sv[jj*33+dd];
        g_qg[h*(LTOT*DHEAD) + (win*16 + ii)*DHEAD + dd] = acc;
    }
}

// ---------------- kernel 2.5: split fp32 -> bf16 hi/lo (Q scaled, K, V^T) ----------------
__global__ void prep_kernel() {
    int g = blockIdx.x*128 + threadIdx.x;     // 0..12799
    int h = g / LTOT, r = g % LTOT;
    const float* q = g_qg + (size_t)g*DHEAD;
    __nv_bfloat16* qd = g_qs + (size_t)g*64;
    __nv_bfloat16* kd = g_ks + (size_t)g*64;
    __nv_bfloat16* vth = g_vt + ((size_t)(h*2+0)*DHEAD)*LTOT + r;
    __nv_bfloat16* vtl = g_vt + ((size_t)(h*2+1)*DHEAD)*LTOT + r;
    #pragma unroll
    for (int d = 0; d < DHEAD; d++) {
        float kv = q[d];
        __nv_bfloat16 kh = __float2bfloat16_rn(kv);
        __nv_bfloat16 kl = __float2bfloat16_rn(kv - __bfloat162float(kh));
        kd[d] = kh; kd[32+d] = kl;
        vth[d*LTOT] = kh; vtl[d*LTOT] = kl;
        float qv = kv * QSCL;
        __nv_bfloat16 qh = __float2bfloat16_rn(qv);
        qd[d] = qh; qd[32+d] = __float2bfloat16_rn(qv - __bfloat162float(qh));
    }
}

// ---------------- kernel 3: persistent flash attention on mma.sync bf16 ----------------
// grid = 296 blocks x 256 thr (8 warps x 16 rows = 128-row q-tiles).
// Work = 10000 units (100 row-groups x 100 key-tiles) split contiguously.
__global__ void __launch_bounds__(256, 2) flashmma_kernel() {
    __shared__ __align__(16) char smem[2*BUFB];
    const int tid = threadIdx.x, w = tid >> 5, lane = tid & 31;
    const int tg = lane >> 2, tc = lane & 3;            // groupID, threadInGroup
    const int b = blockIdx.x;
    int u0 = (b * UTOT) / G_BLOCKS;
    const int u1 = ((b + 1) * UTOT) / G_BLOCKS;
    const uint32_t sbase = smem_u32(smem);

    // ---- cooperative tile load for (head, key-tile) into buffer ----
    auto load_tiles = [&](int h, int kt, int buf) {
        uint32_t db = sbase + buf*BUFB;
        const char* kg = (const char*)(g_ks + ((size_t)h*LTOT + kt*KT)*64);
        #pragma unroll
        for (int j = 0; j < 2; j++) {
            int i = tid + j*256;                        // 0..511
            int r = i >> 3, half = (i >> 2) & 1, c = i & 3;
            cp_async16(db + (half ? B_KL : B_KH) + r*80 + c*16,
                       kg + r*128 + half*64 + c*16);
        }
        #pragma unroll
        for (int j = 0; j < 2; j++) {
            int i = tid + j*256;                        // sp2 x d32 x kg8
            int vsp = i >> 8, rem = i & 255, d = rem >> 3, kgi = rem & 7;
            const char* src = (const char*)(g_vt + ((size_t)(h*2+vsp)*DHEAD + d)*LTOT + kt*KT) + kgi*16;
            cp_async16(db + (vsp ? B_VTL : B_VTH) + d*144 + kgi*16, src);
        }
    };

    { int g0 = u0 / UPR; load_tiles(g0 / 50, u0 % UPR, 0); CP_COMMIT(); }
    int buf = 0;

    while (u0 < u1) {
        const int g = u0 / UPR, h = g / 50, qt = g % 50;
        const int t0 = u0 % UPR;
        const int tend = (UPR < t0 + (u1 - u0)) ? UPR : (t0 + (u1 - u0));

        // ---- Q fragments (A of m16n8k16), rows qt*128 + w*16 .., hi/lo splits ----
        uint32_t qh[2][4], ql[2][4];
        {
            const uint32_t* qb = (const uint32_t*)g_qs + ((size_t)h*LTOT + qt*128 + w*16)*32;
            #pragma unroll
            for (int ks = 0; ks < 2; ks++) {
                int ca = ks*8 + tc;
                qh[ks][0] = qb[tg*32     + ca];
                qh[ks][1] = qb[(tg+8)*32 + ca];
                qh[ks][2] = qb[tg*32     + ca + 4];
                qh[ks][3] = qb[(tg+8)*32 + ca + 4];
                ql[ks][0] = qb[tg*32     + 16 + ca];
                ql[ks][1] = qb[(tg+8)*32 + 16 + ca];
                ql[ks][2] = qb[tg*32     + 16 + ca + 4];
                ql[ks][3] = qb[(tg+8)*32 + 16 + ca + 4];
            }
        }

        float oacc[4][4];
        #pragma unroll
        for (int i = 0; i < 4; i++)
            #pragma unroll
            for (int j = 0; j < 4; j++) oacc[i][j] = 0.f;
        float lr = 0.f, lr8 = 0.f;

        for (int t = t0; t < tend; t++) {
            int unext = u0 + (t - t0) + 1;
            if (unext < u1) {
                int gn = unext / UPR;
                load_tiles(gn / 50, unext % UPR, buf ^ 1);
                CP_COMMIT();
                asm volatile("cp.async.wait_group 1;" ::: "memory");
            } else {
                asm volatile("cp.async.wait_group 0;" ::: "memory");
            }
            __syncthreads();

            const uint32_t* KH  = (const uint32_t*)(smem + buf*BUFB + B_KH);
            const uint32_t* KL  = (const uint32_t*)(smem + buf*BUFB + B_KL);
            const uint32_t* VTH = (const uint32_t*)(smem + buf*BUFB + B_VTH);
            const uint32_t* VTL = (const uint32_t*)(smem + buf*BUFB + B_VTL);

            // ---- S = Q K^T : 8 ntiles of 8 keys, fp32 accum ----
            float sacc[8][4];
            #pragma unroll
            for (int nt = 0; nt < 8; nt++) {
                sacc[nt][0] = sacc[nt][1] = sacc[nt][2] = sacc[nt][3] = 0.f;
                #pragma unroll
                for (int ks = 0; ks < 2; ks++) {
                    int ad = (nt*8 + tg)*20 + ks*8 + tc;
                    uint32_t bh0 = KH[ad], bh1 = KH[ad+4];
                    uint32_t bl0 = KL[ad], bl1 = KL[ad+4];
                    mma_bf16(sacc[nt], qh[ks], bh0, bh1);
                    mma_bf16(sacc[nt], qh[ks], bl0, bl1);
                    mma_bf16(sacc[nt], ql[ks], bh0, bh1);
                }
            }

            // ---- epilogue: p = 2^s; pack into A fragments (hi/lo split) ----
            uint32_t pha[4][4], pla[4][4];
            #pragma unroll
            for (int kt2 = 0; kt2 < 4; kt2++) {
                float p0 = ex2f(sacc[2*kt2][0]),   p1 = ex2f(sacc[2*kt2][1]);
                float p2 = ex2f(sacc[2*kt2][2]),   p3 = ex2f(sacc[2*kt2][3]);
                float p4 = ex2f(sacc[2*kt2+1][0]), p5 = ex2f(sacc[2*kt2+1][1]);
                float p6 = ex2f(sacc[2*kt2+1][2]), p7 = ex2f(sacc[2*kt2+1][3]);
                lr  += (p0 + p1) + (p4 + p5);
                lr8 += (p2 + p3) + (p6 + p7);
                uint32_t u0p = packbf(p0, p1), u1p = packbf(p2, p3);
                uint32_t u2p = packbf(p4, p5), u3p = packbf(p6, p7);
                pha[kt2][0] = u0p; pha[kt2][1] = u1p; pha[kt2][2] = u2p; pha[kt2][3] = u3p;
                pla[kt2][0] = packbf(p0 - __uint_as_float(u0p << 16), p1 - __uint_as_float(u0p & 0xffff0000u));
                pla[kt2][1] = packbf(p2 - __uint_as_float(u1p << 16), p3 - __uint_as_float(u1p & 0xffff0000u));
                pla[kt2][2] = packbf(p4 - __uint_as_float(u2p << 16), p5 - __uint_as_float(u2p & 0xffff0000u));
                pla[kt2][3] = packbf(p6 - __uint_as_float(u3p << 16), p7 - __uint_as_float(u3p & 0xffff0000u));
            }

            // ---- O += P V ----
            #pragma unroll
            for (int dt = 0; dt < 4; dt++) {
                #pragma unroll
                for (int kt2 = 0; kt2 < 4; kt2++) {
                    int ad = (dt*8 + tg)*36 + kt2*8 + tc;
                    uint32_t vh0 = VTH[ad], vh1 = VTH[ad+4];
                    uint32_t vl0 = VTL[ad], vl1 = VTL[ad+4];
                    mma_bf16(oacc[dt], pha[kt2], vh0, vh1);
                    mma_bf16(oacc[dt], pha[kt2], vl0, vl1);
                    mma_bf16(oacc[dt], pla[kt2], vh0, vh1);
                }
            }
            __syncthreads();
            buf ^= 1;
        }

        // ---- reduce l across the quad and flush this row-group segment ----
        lr  += __shfl_xor_sync(0xffffffffu, lr, 1);
        lr  += __shfl_xor_sync(0xffffffffu, lr, 2);
        lr8 += __shfl_xor_sync(0xffffffffu, lr8, 1);
        lr8 += __shfl_xor_sync(0xffffffffu, lr8, 2);

        const int b_first = (g*UPR*G_BLOCKS + G_BLOCKS - 1) / UTOT;  // block owning unit g*UPR
        const int slot = b - b_first;                                 // 0..NSLOT-1
        const int rowa = w*16 + tg, rowb = rowa + 8;
        const int pbase = (g*NSLOT + slot)*128;
        if (tc == 0) { g_pl[pbase + rowa] = lr; g_pl[pbase + rowb] = lr8; }
        float2* pa  = (float2*)(g_po + ((size_t)(pbase + rowa))*DHEAD);
        float2* pbv = (float2*)(g_po + ((size_t)(pbase + rowb))*DHEAD);
        #pragma unroll
        for (int dt = 0; dt < 4; dt++) {
            pa [dt*4 + tc] = make_float2(oacc[dt][0], oacc[dt][1]);
            pbv[dt*4 + tc] = make_float2(oacc[dt][2], oacc[dt][3]);
        }

        u0 += tend - t0;
    }
}

// ---------------- kernel 4: merge partial slots (plain sum + normalize) ----------------
__global__ void merge_kernel() {
    int t = blockIdx.x*256 + threadIdx.x;        // 12800 rows x 8 f4
    int rowf = t >> 3, f4 = t & 7;
    int h = rowf / LTOT, rr = rowf % LTOT;
    int qt = rr >> 7, rowlocal = rr & 127;
    int g = h*50 + qt;
    int b_first = (g*UPR*G_BLOCKS + G_BLOCKS - 1) / UTOT;
    int b_last  = ((g+1)*UPR*G_BLOCKS - 1) / UTOT;
    int ns = b_last - b_first + 1;               // 1..NSLOT
    float l = 0.f;
    float4 acc = make_float4(0.f, 0.f, 0.f, 0.f);
    for (int s = 0; s < ns; s++) {
        int pbase = (g*NSLOT + s)*128 + rowlocal;
        l += g_pl[pbase];
        float4 v = *(const float4*)(g_po + (size_t)pbase*DHEAD + f4*4);
        acc.x += v.x; acc.y += v.y; acc.z += v.z; acc.w += v.w;
    }
    float inv = 1.f / l;
    *(float4*)(g_og + (size_t)rowf*DHEAD + f4*4) =
        make_float4(acc.x*inv, acc.y*inv, acc.z*inv, acc.w*inv);
}

// ---------------- kernel 5: overlap-average gather + proj conv + residual ----------------
__global__ void final_kernel(const float* __restrict__ x,
                             const float* __restrict__ Wp, const float* __restrict__ bp,
                             const float* __restrict__ pa_p, float* __restrict__ out) {
    __shared__ __align__(16) float sg[64];
    int p = blockIdx.x;
    int y = p / HW, xq = p % HW;
    int yp = y + 1, xp = xq + 1;
    int c = threadIdx.x;
    int h = c >> 5, dd = c & 31;
    int sylo = yp - 3; if (sylo < 0) sylo = 0; sylo += (sylo & 1);
    int syhi = yp > 38 ? 38 : yp;  syhi -= (syhi & 1);
    int sxlo = xp - 3; if (sxlo < 0) sxlo = 0; sxlo += (sxlo & 1);
    int sxhi = xp > 38 ? 38 : xp;  sxhi -= (sxhi & 1);
    float acc = 0.f; int cnt = 0;
    for (int sy = sylo; sy <= syhi; sy += 2)
        for (int sx = sxlo; sx <= sxhi; sx += 2) {
            int ty = yp - sy, tx = xp - sx;
            int lw = ((sy >> 1)*NH + (sx >> 1))*NTOK + ty*4 + tx;
            acc += g_og[(h*LTOT + lw)*DHEAD + dd];
            cnt++;
        }
    sg[c] = acc / ((float)cnt + 1e-6f);
    __syncthreads();
    float a = 2.f / (1.f + __expf(-(*pa_p)));
    float pr = bp[c];
    const float4* wrow = (const float4*)(Wp + c*64);
    #pragma unroll
    for (int i = 0; i < 16; i++) {
        float4 w = wrow[i];
        float4 g = *(const float4*)(sg + i*4);
        pr += w.x*g.x + w.y*g.y + w.z*g.z + w.w*g.w;
    }
    int oi = c*1600 + y*HW + xq;
    out[oi] = x[oi] + a*pr;
}

// ---------------- launcher ----------------
extern "C" void kernel_launch(void* const* d_in, const int* in_sizes, int n_in,
                              void* d_out, int out_size) {
    (void)in_sizes; (void)n_in; (void)out_size;
    const float* x     = (const float*)d_in[0];
    const float* z     = (const float*)d_in[1];
    const float* Wqkv  = (const float*)d_in[2];
    const float* bqkv  = (const float*)d_in[3];
    const float* Wqkz  = (const float*)d_in[4];
    const float* bqkz  = (const float*)d_in[5];
    const float* Wproj = (const float*)d_in[6];
    const float* bproj = (const float*)d_in[7];
    const float* pa    = (const float*)d_in[8];
    const float* pbeta = (const float*)d_in[9];
    float* out = (float*)d_out;

    proj_kernel<<<HP, 320>>>(x, z, Wqkv, bqkv, Wqkz, bqkz);
    local_attn_kernel<<<dim3(NWIN, HEADS), 256>>>(pbeta);
    prep_kernel<<<100, 128>>>();
    flashmma_kernel<<<G_BLOCKS, 256>>>();
    merge_kernel<<<LTOT*HEADS*8/256, 256>>>();
    final_kernel<<<HW*HW, 64>>>(x, Wproj, bproj, pa, out);
}